// round 1
// baseline (speedup 1.0000x reference)
#include <cuda_runtime.h>
#include <cstdint>

// Problem constants
#define Bb 4
#define Nn 10000
#define KR 5
#define KA 8
#define Cc 32
#define Oo 64
#define Kk 2

#define Mdim 40000        // B*N
#define Kdim 1280         // KR*KA*C
#define Ndim 512          // KA(rot)*O

// GEMM tiling
#define BM 128
#define BN 128
#define BK 16
#define NTHREADS 256

// Scratch (device globals — no allocation allowed)
__device__ float g_X[(size_t)Mdim * Kdim];       // 204.8 MB
__device__ float g_W2[Kdim * Ndim];              // 2.6 MB
__device__ float g_biasK[Oo];

// ---------------------------------------------------------------------------
// Prep: W2[k][j] = sum_g kernels[g, p, (q+r)&7, o, c]
//   k = (p*KA+q)*C + c ; j = r*O + o
// kernels layout: [g][p][q][o][c] strides: c=1, o=32, q=2048, p=16384, g=81920
// ---------------------------------------------------------------------------
__global__ void prep_w2_kernel(const float* __restrict__ kernels) {
    int t = blockIdx.x * blockDim.x + threadIdx.x;
    if (t >= Kdim * Ndim) return;
    int j = t & (Ndim - 1);
    int k = t >> 9;
    int c  = k & 31;
    int pq = k >> 5;
    int q  = pq & 7;
    int p  = pq >> 3;
    int o  = j & 63;
    int r  = j >> 6;
    int qr = (q + r) & 7;
    int base = p * 16384 + qr * 2048 + o * 32 + c;
    g_W2[t] = kernels[base] + kernels[81920 + base];
}

// biasK[o] = K * sum_{p,q} bias[p,q,o]
__global__ void prep_bias_kernel(const float* __restrict__ bias) {
    int o = threadIdx.x;
    float s = 0.f;
#pragma unroll
    for (int pq = 0; pq < KR * KA; pq++) s += bias[pq * Oo + o];
    g_biasK[o] = (float)Kk * s;
}

// ---------------------------------------------------------------------------
// Gather: X[m][pq*32+c] = sum_v w_v * signal[b, idx_v, c]
// One warp per (m, pq); lane = channel. Signal reads are 128B coalesced & L2-hot.
// barycentric layout: [b][n][p][q][v][{idx,w}], innermost stride 1
// ---------------------------------------------------------------------------
__global__ void gather_kernel(const float* __restrict__ signal,
                              const float* __restrict__ bary) {
    int pair = blockIdx.x * 8 + (threadIdx.x >> 5);
    int lane = threadIdx.x & 31;
    if (pair >= Mdim * (KR * KA)) return;
    int m  = pair / (KR * KA);
    int pq = pair - m * (KR * KA);
    int b = m / Nn;
    int n = m - b * Nn;

    const float* bb = bary + (size_t)b * (Nn * KR * KA * 6)
                           + (size_t)n * (KR * KA * 6) + pq * 6;
    const float* sb = signal + (size_t)b * (Nn * Cc);

    float acc = 0.f;
#pragma unroll
    for (int v = 0; v < 3; v++) {
        int   idx = (int)bb[2 * v];     // broadcast load (same addr across warp)
        float w   = bb[2 * v + 1];
        acc = fmaf(w, sb[(size_t)idx * Cc + lane], acc);
    }
    g_X[(size_t)m * Kdim + pq * Cc + lane] = acc;
}

// ---------------------------------------------------------------------------
// SGEMM: Y = X[40000x1280] * W2[1280x512], epilogue adds biasK and scatters to
// out[b][r][n][o] (o=1, n=64, r=640000, b=5120000 strides).
// 128x128x16 tiles, 256 threads, 8x8 per thread, single smem buffer with
// global-load prefetch overlapping compute.
// ---------------------------------------------------------------------------
__global__ void __launch_bounds__(NTHREADS)
gemm_kernel(float* __restrict__ out) {
    __shared__ __align__(16) float As[BK][BM];   // transposed A tile
    __shared__ __align__(16) float Bs[BK][BN];

    const int tid = threadIdx.x;
    const int m0 = blockIdx.x * BM;
    const int j0 = blockIdx.y * BN;

    const int ty = tid >> 4;   // 0..15 -> row group
    const int tx = tid & 15;   // 0..15 -> col group

    // A-load mapping: 512 float4 per tile, 2 per thread
    const int a_row0 = (tid) >> 2;          // 0..63
    const int a_c4_0 = (tid) & 3;
    const int a_row1 = (tid + 256) >> 2;    // 64..127
    const int a_c4_1 = (tid + 256) & 3;
    // B-load mapping
    const int b_row0 = (tid) >> 5;          // 0..7
    const int b_col0 = (tid) & 31;
    const int b_row1 = (tid + 256) >> 5;    // 8..15
    const int b_col1 = (tid + 256) & 31;

    float4 pa0, pa1, pb0, pb1;

    auto loadG = [&](int kt) {
        int k = kt * BK;
        int m;
        m = m0 + a_row0;
        pa0 = (m < Mdim) ? *(const float4*)&g_X[(size_t)m * Kdim + k + a_c4_0 * 4]
                         : make_float4(0.f, 0.f, 0.f, 0.f);
        m = m0 + a_row1;
        pa1 = (m < Mdim) ? *(const float4*)&g_X[(size_t)m * Kdim + k + a_c4_1 * 4]
                         : make_float4(0.f, 0.f, 0.f, 0.f);
        pb0 = *(const float4*)&g_W2[(size_t)(k + b_row0) * Ndim + j0 + b_col0 * 4];
        pb1 = *(const float4*)&g_W2[(size_t)(k + b_row1) * Ndim + j0 + b_col1 * 4];
    };
    auto storeS = [&]() {
        As[a_c4_0 * 4 + 0][a_row0] = pa0.x;
        As[a_c4_0 * 4 + 1][a_row0] = pa0.y;
        As[a_c4_0 * 4 + 2][a_row0] = pa0.z;
        As[a_c4_0 * 4 + 3][a_row0] = pa0.w;
        As[a_c4_1 * 4 + 0][a_row1] = pa1.x;
        As[a_c4_1 * 4 + 1][a_row1] = pa1.y;
        As[a_c4_1 * 4 + 2][a_row1] = pa1.z;
        As[a_c4_1 * 4 + 3][a_row1] = pa1.w;
        *(float4*)&Bs[b_row0][b_col0 * 4] = pb0;
        *(float4*)&Bs[b_row1][b_col1 * 4] = pb1;
    };

    float acc[8][8];
#pragma unroll
    for (int i = 0; i < 8; i++)
#pragma unroll
        for (int j = 0; j < 8; j++) acc[i][j] = 0.f;

    const int NTILES = Kdim / BK;   // 80
    loadG(0);
    storeS();
    __syncthreads();

    for (int kt = 0; kt < NTILES; kt++) {
        if (kt + 1 < NTILES) loadG(kt + 1);

#pragma unroll
        for (int kk = 0; kk < BK; kk++) {
            float a[8], bv[8];
            *(float4*)&a[0]  = *(const float4*)&As[kk][ty * 8];
            *(float4*)&a[4]  = *(const float4*)&As[kk][ty * 8 + 4];
            *(float4*)&bv[0] = *(const float4*)&Bs[kk][tx * 8];
            *(float4*)&bv[4] = *(const float4*)&Bs[kk][tx * 8 + 4];
#pragma unroll
            for (int i = 0; i < 8; i++)
#pragma unroll
                for (int j = 0; j < 8; j++)
                    acc[i][j] = fmaf(a[i], bv[j], acc[i][j]);
        }
        __syncthreads();
        if (kt + 1 < NTILES) {
            storeS();
        }
        __syncthreads();
    }

    // epilogue: bias + scatter to out[b][r][n][o]
    float bk[8];
#pragma unroll
    for (int j = 0; j < 8; j++) bk[j] = g_biasK[(j0 + tx * 8 + j) & 63];

#pragma unroll
    for (int i = 0; i < 8; i++) {
        int m = m0 + ty * 8 + i;
        if (m >= Mdim) continue;
        int b = m / Nn;
        int n = m - b * Nn;
#pragma unroll
        for (int jj = 0; jj < 8; jj += 4) {
            int j = j0 + tx * 8 + jj;
            int r = j >> 6;
            int o = j & 63;
            float4 v;
            v.x = acc[i][jj + 0] + bk[jj + 0];
            v.y = acc[i][jj + 1] + bk[jj + 1];
            v.z = acc[i][jj + 2] + bk[jj + 2];
            v.w = acc[i][jj + 3] + bk[jj + 3];
            size_t oi = (size_t)b * (KA * (size_t)Nn * Oo)
                      + (size_t)r * ((size_t)Nn * Oo)
                      + (size_t)n * Oo + o;
            *(float4*)&out[oi] = v;
        }
    }
}

// ---------------------------------------------------------------------------
extern "C" void kernel_launch(void* const* d_in, const int* in_sizes, int n_in,
                              void* d_out, int out_size) {
    const float* signal  = (const float*)d_in[0];
    const float* bary    = (const float*)d_in[1];
    const float* kernels = (const float*)d_in[2];
    const float* bias    = (const float*)d_in[3];
    float* out = (float*)d_out;

    // 1) weight prep: W2 [1280 x 512]
    prep_w2_kernel<<<(Kdim * Ndim + 255) / 256, 256>>>(kernels);
    // 2) bias prep
    prep_bias_kernel<<<1, Oo>>>(bias);
    // 3) gather -> X [40000 x 1280]
    {
        int pairs = Mdim * KR * KA;          // 1.6M warps
        int blocks = (pairs + 7) / 8;        // 8 warps per 256-thread block
        gather_kernel<<<blocks, 256>>>(signal, bary);
    }
    // 4) GEMM + bias + scatter
    {
        dim3 grid((Mdim + BM - 1) / BM, Ndim / BN);  // (313, 4)
        gemm_kernel<<<grid, NTHREADS>>>(out);
    }
}

// round 3
// speedup vs baseline: 2.4676x; 2.4676x over previous
#include <cuda_runtime.h>
#include <cuda_bf16.h>
#include <cstdint>

// ---------------- problem constants ----------------
#define Nn   10000
#define KRr  5
#define KAa  8
#define Cc   32
#define Oo   64

#define Mdim 40000            // B*N
#define Kdim 1280             // KR*KA*C
#define Ndim 512              // KA(rot)*O
#define Mpad 40064            // 313 * 128

// ---------------- GEMM tiling ----------------
#define TILE_M 128
#define TILE_N 128
#define KCHUNK 64                  // bf16 per K chunk (128 B per row)
#define NCHUNK (Kdim / KCHUNK)     // 20
#define A_HI 0
#define A_LO 16384
#define B_HI 32768
#define B_LO 49152
#define STAGE_BYTES 65536
#define GEMM_SMEM (2 * STAGE_BYTES)   // 131072

// ---------------- device scratch ----------------
__device__ __nv_bfloat16 g_Xhi[(size_t)Mpad * Kdim];
__device__ __nv_bfloat16 g_Xlo[(size_t)Mpad * Kdim];
__device__ __nv_bfloat16 g_Wth[(size_t)Ndim * Kdim];   // W2^T hi [n][k]
__device__ __nv_bfloat16 g_Wtl[(size_t)Ndim * Kdim];
__device__ float         g_biasK[Oo];

// ---------------- helpers ----------------
__device__ __forceinline__ uint32_t smem_u32(const void* p) {
    uint32_t a;
    asm("{ .reg .u64 t; cvta.to.shared.u64 t, %1; cvt.u32.u64 %0, t; }" : "=r"(a) : "l"(p));
    return a;
}
__device__ __forceinline__ void cp16(uint32_t dst, const void* src) {
    asm volatile("cp.async.cg.shared.global [%0], [%1], 16;" :: "r"(dst), "l"(src));
}
__device__ __forceinline__ void ldsm_x4(uint32_t addr, uint32_t& r0, uint32_t& r1,
                                        uint32_t& r2, uint32_t& r3) {
    asm volatile("ldmatrix.sync.aligned.m8n8.x4.shared.b16 {%0,%1,%2,%3}, [%4];"
                 : "=r"(r0), "=r"(r1), "=r"(r2), "=r"(r3) : "r"(addr));
}
__device__ __forceinline__ void mma16816(float* c, uint32_t a0, uint32_t a1,
                                         uint32_t a2, uint32_t a3,
                                         uint32_t b0, uint32_t b1) {
    asm volatile(
        "mma.sync.aligned.m16n8k16.row.col.f32.bf16.bf16.f32 "
        "{%0,%1,%2,%3}, {%4,%5,%6,%7}, {%8,%9}, {%0,%1,%2,%3};"
        : "+f"(c[0]), "+f"(c[1]), "+f"(c[2]), "+f"(c[3])
        : "r"(a0), "r"(a1), "r"(a2), "r"(a3), "r"(b0), "r"(b1));
}

// ---------------------------------------------------------------------------
// Prep W2^T: Wt[n=r*64+o][k=(p*8+q)*32+c] = sum_g kernels[g,p,(q+r)&7,o,c]
// ---------------------------------------------------------------------------
__global__ void prep_w2_kernel(const float* __restrict__ kernels) {
    int n = blockIdx.x;
    int r = n >> 6, o = n & 63;
    for (int k = threadIdx.x; k < Kdim; k += blockDim.x) {
        int c = k & 31, pq = k >> 5, q = pq & 7, p = pq >> 3;
        int qr = (q + r) & 7;
        int base = p * 16384 + qr * 2048 + o * 32 + c;
        float w = kernels[base] + kernels[81920 + base];
        __nv_bfloat16 hi = __float2bfloat16(w);
        __nv_bfloat16 lo = __float2bfloat16(w - __bfloat162float(hi));
        g_Wth[(size_t)n * Kdim + k] = hi;
        g_Wtl[(size_t)n * Kdim + k] = lo;
    }
}

__global__ void prep_bias_kernel(const float* __restrict__ bias) {
    int o = threadIdx.x;
    float s = 0.f;
#pragma unroll
    for (int pq = 0; pq < KRr * KAa; pq++) s += bias[pq * Oo + o];
    g_biasK[o] = 2.0f * s;
}

// ---------------------------------------------------------------------------
// Gather -> X hi/lo bf16. One warp per (m, pq); lane = channel.
// ---------------------------------------------------------------------------
__global__ void gather_kernel(const float* __restrict__ signal,
                              const float* __restrict__ bary) {
    int pair = blockIdx.x * 8 + (threadIdx.x >> 5);
    int lane = threadIdx.x & 31;
    if (pair >= Mdim * (KRr * KAa)) return;
    int m  = pair / (KRr * KAa);
    int pq = pair - m * (KRr * KAa);
    int b = m / Nn;
    int n = m - b * Nn;

    const float* bb = bary + (size_t)b * (Nn * KRr * KAa * 6)
                           + (size_t)n * (KRr * KAa * 6) + pq * 6;
    const float* sb = signal + (size_t)b * (Nn * Cc);

    float acc = 0.f;
#pragma unroll
    for (int v = 0; v < 3; v++) {
        int   idx = (int)bb[2 * v];
        float w   = bb[2 * v + 1];
        acc = fmaf(w, sb[(size_t)idx * Cc + lane], acc);
    }
    __nv_bfloat16 hi = __float2bfloat16(acc);
    __nv_bfloat16 lo = __float2bfloat16(acc - __bfloat162float(hi));
    size_t xo = (size_t)m * Kdim + pq * Cc + lane;
    g_Xhi[xo] = hi;
    g_Xlo[xo] = lo;
}

// ---------------------------------------------------------------------------
// HMMA GEMM: Y = X[Mpad x 1280] * W2T^T -> [Mpad x 512]
// CTA: 128x128, 8 warps (4m x 2n), warp tile 32x64, mma m16n8k16 bf16.
// 3 MMAs per fragment pair: Ah*Bh + Ah*Bl + Al*Bh.
// ---------------------------------------------------------------------------
__global__ void __launch_bounds__(256, 1)
gemm_mma_kernel(float* __restrict__ out) {
    extern __shared__ __align__(1024) char smem[];
    const uint32_t sb0 = smem_u32(smem);
    const int tid  = threadIdx.x;
    const int wid  = tid >> 5;
    const int lane = tid & 31;
    const int wm = wid & 3;          // 0..3  (m quadrant, 32 rows)
    const int wn = wid >> 2;         // 0..1  (n half, 64 cols)

    const int j0 = blockIdx.x * TILE_N;   // n-split fastest -> A-tile L2 reuse
    const int m0 = blockIdx.y * TILE_M;

    // stage loader: Ah, Al (128 rows), Bh, Bl (128 rows), SW128-style XOR swizzle
    auto load_stage = [&](int c) {
        const int k0 = c * KCHUNK;
        const uint32_t sb = sb0 + (c & 1) * STAGE_BYTES;
#pragma unroll
        for (int i = 0; i < 4; i++) {
            int e = tid + i * 256;
            int row = e >> 3, seg = e & 7;
            uint32_t doff = row * 128 + ((seg ^ (row & 7)) << 4);
            size_t aoff = (size_t)(m0 + row) * Kdim + k0 + seg * 8;
            size_t boff = (size_t)(j0 + row) * Kdim + k0 + seg * 8;
            cp16(sb + A_HI + doff, g_Xhi + aoff);
            cp16(sb + A_LO + doff, g_Xlo + aoff);
            cp16(sb + B_HI + doff, g_Wth + boff);
            cp16(sb + B_LO + doff, g_Wtl + boff);
        }
        asm volatile("cp.async.commit_group;" ::: "memory");
    };

    float acc[2][8][4];
#pragma unroll
    for (int mt = 0; mt < 2; mt++)
#pragma unroll
        for (int nt = 0; nt < 8; nt++)
#pragma unroll
            for (int i = 0; i < 4; i++) acc[mt][nt][i] = 0.f;

    load_stage(0);

    // precomputed fragment address offsets (within a stage buffer)
    const int a_row = wm * 32 + (lane & 15);          // + mt*16
    const int a_sel = lane >> 4;                      // k-seg add
    const int b_row = wn * 64 + (lane & 15);          // + bt*16
    const int b_sel = lane >> 4;

    for (int c = 0; c < NCHUNK; c++) {
        if (c + 1 < NCHUNK) load_stage(c + 1);
        if (c + 1 < NCHUNK) asm volatile("cp.async.wait_group 1;" ::: "memory");
        else                asm volatile("cp.async.wait_group 0;" ::: "memory");
        __syncthreads();

        const uint32_t sb = sb0 + (c & 1) * STAGE_BYTES;

#pragma unroll
        for (int ks = 0; ks < 4; ks++) {
            const int kseg = ks * 2;
            // ---- A fragments (hi & lo), 2 m-tiles
            uint32_t ah[2][4], al[2][4];
#pragma unroll
            for (int mt = 0; mt < 2; mt++) {
                int r = a_row + mt * 16;
                int s = kseg + a_sel;
                uint32_t off = r * 128 + ((s ^ (r & 7)) << 4);
                ldsm_x4(sb + A_HI + off, ah[mt][0], ah[mt][1], ah[mt][2], ah[mt][3]);
                ldsm_x4(sb + A_LO + off, al[mt][0], al[mt][1], al[mt][2], al[mt][3]);
            }
            // ---- B fragments (hi & lo), 8 n-tiles via 4 x4 loads each
            uint32_t bh[8][2], bl[8][2];
#pragma unroll
            for (int bt = 0; bt < 4; bt++) {
                int r = b_row + bt * 16;
                int s = kseg + b_sel;
                uint32_t off = r * 128 + ((s ^ (r & 7)) << 4);
                uint32_t r0, r1, r2, r3;
                ldsm_x4(sb + B_HI + off, r0, r1, r2, r3);
                bh[2 * bt][0] = r0; bh[2 * bt][1] = r2;
                bh[2 * bt + 1][0] = r1; bh[2 * bt + 1][1] = r3;
                ldsm_x4(sb + B_LO + off, r0, r1, r2, r3);
                bl[2 * bt][0] = r0; bl[2 * bt][1] = r2;
                bl[2 * bt + 1][0] = r1; bl[2 * bt + 1][1] = r3;
            }
            // ---- MMAs
#pragma unroll
            for (int mt = 0; mt < 2; mt++)
#pragma unroll
                for (int nt = 0; nt < 8; nt++) {
                    mma16816(acc[mt][nt], ah[mt][0], ah[mt][1], ah[mt][2], ah[mt][3],
                             bh[nt][0], bh[nt][1]);
                    mma16816(acc[mt][nt], ah[mt][0], ah[mt][1], ah[mt][2], ah[mt][3],
                             bl[nt][0], bl[nt][1]);
                    mma16816(acc[mt][nt], al[mt][0], al[mt][1], al[mt][2], al[mt][3],
                             bh[nt][0], bh[nt][1]);
                }
        }
        __syncthreads();
    }

    // ---- epilogue: C frag (row = lane/4 [+8], col = 2*(lane%4)), add bias, scatter
    const int r_out = (j0 + wn * 64) >> 6;           // rotation index (constant/warp)
    const int ob = (lane & 3) * 2;
    float2 bias2[8];
#pragma unroll
    for (int nt = 0; nt < 8; nt++) {
        bias2[nt].x = g_biasK[nt * 8 + ob];
        bias2[nt].y = g_biasK[nt * 8 + ob + 1];
    }

#pragma unroll
    for (int mt = 0; mt < 2; mt++) {
#pragma unroll
        for (int half = 0; half < 2; half++) {
            int m = m0 + wm * 32 + mt * 16 + (lane >> 2) + half * 8;
            if (m >= Mdim) continue;
            int b = m / Nn;
            int n = m - b * Nn;
            float* op = out + (size_t)b * ((size_t)KAa * Nn * Oo)
                            + (size_t)r_out * ((size_t)Nn * Oo) + (size_t)n * Oo;
#pragma unroll
            for (int nt = 0; nt < 8; nt++) {
                float2 v;
                v.x = acc[mt][nt][half * 2 + 0] + bias2[nt].x;
                v.y = acc[mt][nt][half * 2 + 1] + bias2[nt].y;
                *(float2*)&op[nt * 8 + ob] = v;
            }
        }
    }
}

// ---------------------------------------------------------------------------
extern "C" void kernel_launch(void* const* d_in, const int* in_sizes, int n_in,
                              void* d_out, int out_size) {
    const float* signal  = (const float*)d_in[0];
    const float* bary    = (const float*)d_in[1];
    const float* kernels = (const float*)d_in[2];
    const float* bias    = (const float*)d_in[3];
    float* out = (float*)d_out;

    prep_w2_kernel<<<Ndim, 256>>>(kernels);
    prep_bias_kernel<<<1, Oo>>>(bias);

    {
        int pairs = Mdim * KRr * KAa;
        int blocks = (pairs + 7) / 8;
        gather_kernel<<<blocks, 256>>>(signal, bary);
    }

    {
        static int smem_set = 0;
        if (!smem_set) {
            cudaFuncSetAttribute(gemm_mma_kernel,
                                 cudaFuncAttributeMaxDynamicSharedMemorySize, GEMM_SMEM);
            smem_set = 1;
        }
        dim3 grid(Ndim / TILE_N, Mpad / TILE_M);   // (4, 313): n-split fastest
        gemm_mma_kernel<<<grid, 256, GEMM_SMEM>>>(out);
    }
}

// round 4
// speedup vs baseline: 4.3279x; 1.7538x over previous
#include <cuda_runtime.h>
#include <cuda_fp16.h>
#include <cstdint>

// ---------------- problem constants ----------------
#define Nn   10000
#define KRr  5
#define KAa  8
#define Cc   32
#define Oo   64

#define Mdim 40000            // B*N
#define Kdim 1280             // KR*KA*C
#define Ndim 512              // KA(rot)*O
#define Mpad 40064            // 313 * 128

// ---------------- GEMM tiling ----------------
#define TILE_M 128
#define TILE_N 128
#define KCHUNK 64                  // fp16 per K chunk (128 B per row)
#define NCHUNK (Kdim / KCHUNK)     // 20
#define A_HI 0
#define A_LO 16384
#define B_HI 32768
#define STAGE_BYTES 49152
#define GEMM_SMEM (2 * STAGE_BYTES)   // 98304

// ---------------- device scratch ----------------
__device__ __half g_Xhi[(size_t)Mpad * Kdim];
__device__ __half g_Xlo[(size_t)Mpad * Kdim];
__device__ __half g_Wh[(size_t)Ndim * Kdim];      // W2^T fp16 [n][k]
__device__ float  g_biasK[Oo];

// ---------------- helpers ----------------
__device__ __forceinline__ uint32_t smem_u32(const void* p) {
    uint32_t a;
    asm("{ .reg .u64 t; cvta.to.shared.u64 t, %1; cvt.u32.u64 %0, t; }" : "=r"(a) : "l"(p));
    return a;
}
__device__ __forceinline__ void cp16(uint32_t dst, const void* src) {
    asm volatile("cp.async.cg.shared.global [%0], [%1], 16;" :: "r"(dst), "l"(src));
}
__device__ __forceinline__ void ldsm_x4(uint32_t addr, uint32_t& r0, uint32_t& r1,
                                        uint32_t& r2, uint32_t& r3) {
    asm volatile("ldmatrix.sync.aligned.m8n8.x4.shared.b16 {%0,%1,%2,%3}, [%4];"
                 : "=r"(r0), "=r"(r1), "=r"(r2), "=r"(r3) : "r"(addr));
}
__device__ __forceinline__ void mma16816(float* c, uint32_t a0, uint32_t a1,
                                         uint32_t a2, uint32_t a3,
                                         uint32_t b0, uint32_t b1) {
    asm volatile(
        "mma.sync.aligned.m16n8k16.row.col.f32.f16.f16.f32 "
        "{%0,%1,%2,%3}, {%4,%5,%6,%7}, {%8,%9}, {%0,%1,%2,%3};"
        : "+f"(c[0]), "+f"(c[1]), "+f"(c[2]), "+f"(c[3])
        : "r"(a0), "r"(a1), "r"(a2), "r"(a3), "r"(b0), "r"(b1));
}

// ---------------------------------------------------------------------------
// Prep W2^T (fp16): Wh[n=r*64+o][k=(p*8+q)*32+c] = sum_g kernels[g,p,(q+r)&7,o,c]
// ---------------------------------------------------------------------------
__global__ void prep_w2_kernel(const float* __restrict__ kernels) {
    int n = blockIdx.x;
    int r = n >> 6, o = n & 63;
    for (int k = threadIdx.x; k < Kdim; k += blockDim.x) {
        int c = k & 31, pq = k >> 5, q = pq & 7, p = pq >> 3;
        int qr = (q + r) & 7;
        int base = p * 16384 + qr * 2048 + o * 32 + c;
        float w = kernels[base] + kernels[81920 + base];
        g_Wh[(size_t)n * Kdim + k] = __float2half_rn(w);
    }
}

__global__ void prep_bias_kernel(const float* __restrict__ bias) {
    int o = threadIdx.x;
    float s = 0.f;
#pragma unroll
    for (int pq = 0; pq < KRr * KAa; pq++) s += bias[pq * Oo + o];
    g_biasK[o] = 2.0f * s;
}

// ---------------------------------------------------------------------------
// Gather -> X hi/lo fp16. One warp per m-row; each iteration covers 2 pq:
// lanes 0-15 -> pq=2j (channels 2l,2l+1), lanes 16-31 -> pq=2j+1.
// Stores are 128B-contiguous half2 words.
// ---------------------------------------------------------------------------
__global__ void gather_kernel(const float* __restrict__ signal,
                              const float* __restrict__ bary) {
    int m = blockIdx.x * 8 + (threadIdx.x >> 5);
    if (m >= Mdim) return;
    const int lane = threadIdx.x & 31;
    const int half = lane >> 4;
    const int cl   = (lane & 15) * 2;

    const int b = m / Nn;
    const int n = m - b * Nn;
    const float* sb = signal + (size_t)b * (Nn * Cc);
    const float* bm = bary + (size_t)(b * Nn + n) * (KRr * KAa * 6);

    uint32_t* xh = (uint32_t*)(g_Xhi + (size_t)m * Kdim);
    uint32_t* xl = (uint32_t*)(g_Xlo + (size_t)m * Kdim);

#pragma unroll 4
    for (int jp = 0; jp < KRr * KAa / 2; jp++) {
        const int pq = 2 * jp + half;
        const float* bb = bm + pq * 6;
        float ax = 0.f, ay = 0.f;
#pragma unroll
        for (int v = 0; v < 3; v++) {
            int   idx = (int)bb[2 * v];
            float w   = bb[2 * v + 1];
            float2 s = *(const float2*)&sb[(size_t)idx * Cc + cl];
            ax = fmaf(w, s.x, ax);
            ay = fmaf(w, s.y, ay);
        }
        __half hx = __float2half_rn(ax);
        __half hy = __float2half_rn(ay);
        __half lx = __float2half_rn(ax - __half2float(hx));
        __half ly = __float2half_rn(ay - __half2float(hy));
        int off = (pq * Cc + cl) >> 1;
        xh[off] = __half2_raw(__halves2half2(hx, hy)).x |
                  ((uint32_t)__half2_raw(__halves2half2(hx, hy)).y << 16);
        xl[off] = __half2_raw(__halves2half2(lx, ly)).x |
                  ((uint32_t)__half2_raw(__halves2half2(lx, ly)).y << 16);
    }
}

// ---------------------------------------------------------------------------
// HMMA GEMM: Y = X[Mpad x 1280] * Wh^T -> [Mpad x 512]
// CTA 128x128, 8 warps (4m x 2n), warp tile 32x64, mma m16n8k16 fp16.
// 2 MMAs per fragment pair: Ah*Bh + Al*Bh.  2 CTAs/SM (96KB smem).
// ---------------------------------------------------------------------------
__global__ void __launch_bounds__(256, 2)
gemm_mma_kernel(float* __restrict__ out) {
    extern __shared__ __align__(1024) char smem[];
    const uint32_t sb0 = smem_u32(smem);
    const int tid  = threadIdx.x;
    const int wid  = tid >> 5;
    const int lane = tid & 31;
    const int wm = wid & 3;          // m quadrant (32 rows)
    const int wn = wid >> 2;         // n half (64 cols)

    const int j0 = blockIdx.x * TILE_N;   // n-split fastest -> A-tile L2 reuse
    const int m0 = blockIdx.y * TILE_M;

    auto load_stage = [&](int c) {
        const int k0 = c * KCHUNK;
        const uint32_t sb = sb0 + (c & 1) * STAGE_BYTES;
#pragma unroll
        for (int i = 0; i < 4; i++) {
            int e = tid + i * 256;
            int row = e >> 3, seg = e & 7;
            uint32_t doff = row * 128 + ((seg ^ (row & 7)) << 4);
            size_t aoff = (size_t)(m0 + row) * Kdim + k0 + seg * 8;
            size_t boff = (size_t)(j0 + row) * Kdim + k0 + seg * 8;
            cp16(sb + A_HI + doff, g_Xhi + aoff);
            cp16(sb + A_LO + doff, g_Xlo + aoff);
            cp16(sb + B_HI + doff, g_Wh + boff);
        }
        asm volatile("cp.async.commit_group;" ::: "memory");
    };

    float acc[2][8][4];
#pragma unroll
    for (int mt = 0; mt < 2; mt++)
#pragma unroll
        for (int nt = 0; nt < 8; nt++)
#pragma unroll
            for (int i = 0; i < 4; i++) acc[mt][nt][i] = 0.f;

    load_stage(0);

    const int a_row = wm * 32 + (lane & 15);
    const int a_sel = lane >> 4;
    const int b_row = wn * 64 + (lane & 15);
    const int b_sel = lane >> 4;

    for (int c = 0; c < NCHUNK; c++) {
        if (c + 1 < NCHUNK) {
            load_stage(c + 1);
            asm volatile("cp.async.wait_group 1;" ::: "memory");
        } else {
            asm volatile("cp.async.wait_group 0;" ::: "memory");
        }
        __syncthreads();

        const uint32_t sb = sb0 + (c & 1) * STAGE_BYTES;

#pragma unroll
        for (int ks = 0; ks < 4; ks++) {
            const int kseg = ks * 2;
            uint32_t ah[2][4], al[2][4];
#pragma unroll
            for (int mt = 0; mt < 2; mt++) {
                int r = a_row + mt * 16;
                int s = kseg + a_sel;
                uint32_t off = r * 128 + ((s ^ (r & 7)) << 4);
                ldsm_x4(sb + A_HI + off, ah[mt][0], ah[mt][1], ah[mt][2], ah[mt][3]);
                ldsm_x4(sb + A_LO + off, al[mt][0], al[mt][1], al[mt][2], al[mt][3]);
            }
            uint32_t bh[8][2];
#pragma unroll
            for (int bt = 0; bt < 4; bt++) {
                int r = b_row + bt * 16;
                int s = kseg + b_sel;
                uint32_t off = r * 128 + ((s ^ (r & 7)) << 4);
                uint32_t r0, r1, r2, r3;
                ldsm_x4(sb + B_HI + off, r0, r1, r2, r3);
                bh[2 * bt][0] = r0; bh[2 * bt][1] = r2;
                bh[2 * bt + 1][0] = r1; bh[2 * bt + 1][1] = r3;
            }
#pragma unroll
            for (int mt = 0; mt < 2; mt++)
#pragma unroll
                for (int nt = 0; nt < 8; nt++) {
                    mma16816(acc[mt][nt], ah[mt][0], ah[mt][1], ah[mt][2], ah[mt][3],
                             bh[nt][0], bh[nt][1]);
                    mma16816(acc[mt][nt], al[mt][0], al[mt][1], al[mt][2], al[mt][3],
                             bh[nt][0], bh[nt][1]);
                }
        }
        __syncthreads();
    }

    // ---- epilogue
    const int r_out = (j0 + wn * 64) >> 6;
    const int ob = (lane & 3) * 2;
    float2 bias2[8];
#pragma unroll
    for (int nt = 0; nt < 8; nt++) {
        bias2[nt].x = g_biasK[nt * 8 + ob];
        bias2[nt].y = g_biasK[nt * 8 + ob + 1];
    }

#pragma unroll
    for (int mt = 0; mt < 2; mt++) {
#pragma unroll
        for (int half = 0; half < 2; half++) {
            int m = m0 + wm * 32 + mt * 16 + (lane >> 2) + half * 8;
            if (m >= Mdim) continue;
            int b = m / Nn;
            int n = m - b * Nn;
            float* op = out + (size_t)b * ((size_t)KAa * Nn * Oo)
                            + (size_t)r_out * ((size_t)Nn * Oo) + (size_t)n * Oo;
#pragma unroll
            for (int nt = 0; nt < 8; nt++) {
                float2 v;
                v.x = acc[mt][nt][half * 2 + 0] + bias2[nt].x;
                v.y = acc[mt][nt][half * 2 + 1] + bias2[nt].y;
                *(float2*)&op[nt * 8 + ob] = v;
            }
        }
    }
}

// ---------------------------------------------------------------------------
extern "C" void kernel_launch(void* const* d_in, const int* in_sizes, int n_in,
                              void* d_out, int out_size) {
    const float* signal  = (const float*)d_in[0];
    const float* bary    = (const float*)d_in[1];
    const float* kernels = (const float*)d_in[2];
    const float* bias    = (const float*)d_in[3];
    float* out = (float*)d_out;

    prep_w2_kernel<<<Ndim, 256>>>(kernels);
    prep_bias_kernel<<<1, Oo>>>(bias);

    gather_kernel<<<(Mdim + 7) / 8, 256>>>(signal, bary);

    {
        static int smem_set = 0;
        if (!smem_set) {
            cudaFuncSetAttribute(gemm_mma_kernel,
                                 cudaFuncAttributeMaxDynamicSharedMemorySize, GEMM_SMEM);
            smem_set = 1;
        }
        dim3 grid(Ndim / TILE_N, Mpad / TILE_M);   // (4, 313)
        gemm_mma_kernel<<<grid, 256, GEMM_SMEM>>>(out);
    }
}

// round 5
// speedup vs baseline: 6.9715x; 1.6108x over previous
#include <cuda_runtime.h>
#include <cuda_fp16.h>
#include <cstdint>

// ---------------- problem constants ----------------
#define Nn   10000
#define KRr  5
#define KAa  8
#define Cc   32
#define Oo   64

#define Mdim 40000            // B*N
#define Kdim 1280             // KR*KA*C
#define Ndim 512              // KA(rot)*O
#define Mpad 40064            // 313 * 128

// ---------------- GEMM tiling ----------------
#define TILE_M 128
#define TILE_N 128
#define KCHUNK 64                  // fp16 per K chunk (128 B per row)
#define NCHUNK (Kdim / KCHUNK)     // 20
#define B_OFF 16384
#define STAGE_BYTES 32768
#define NSTAGE 3
#define GEMM_SMEM (NSTAGE * STAGE_BYTES)   // 98304 -> 2 CTAs/SM

// ---------------- device scratch ----------------
__device__ __half g_Xh[(size_t)Mpad * Kdim];      // 102.6 MB
__device__ __half g_Wh[(size_t)Ndim * Kdim];      // W2^T fp16 [n][k]
__device__ float  g_biasK[Oo];

// ---------------- helpers ----------------
__device__ __forceinline__ uint32_t smem_u32(const void* p) {
    uint32_t a;
    asm("{ .reg .u64 t; cvta.to.shared.u64 t, %1; cvt.u32.u64 %0, t; }" : "=r"(a) : "l"(p));
    return a;
}
__device__ __forceinline__ void cp16(uint32_t dst, const void* src) {
    asm volatile("cp.async.cg.shared.global [%0], [%1], 16;" :: "r"(dst), "l"(src));
}
__device__ __forceinline__ void ldsm_x4(uint32_t addr, uint32_t& r0, uint32_t& r1,
                                        uint32_t& r2, uint32_t& r3) {
    asm volatile("ldmatrix.sync.aligned.m8n8.x4.shared.b16 {%0,%1,%2,%3}, [%4];"
                 : "=r"(r0), "=r"(r1), "=r"(r2), "=r"(r3) : "r"(addr));
}
__device__ __forceinline__ void mma16816(float* c, const uint32_t* a,
                                         uint32_t b0, uint32_t b1) {
    asm volatile(
        "mma.sync.aligned.m16n8k16.row.col.f32.f16.f16.f32 "
        "{%0,%1,%2,%3}, {%4,%5,%6,%7}, {%8,%9}, {%0,%1,%2,%3};"
        : "+f"(c[0]), "+f"(c[1]), "+f"(c[2]), "+f"(c[3])
        : "r"(a[0]), "r"(a[1]), "r"(a[2]), "r"(a[3]), "r"(b0), "r"(b1));
}

// ---------------------------------------------------------------------------
// Prep W2^T (fp16): Wh[n=r*64+o][k=(p*8+q)*32+c] = sum_g kernels[g,p,(q+r)&7,o,c]
// ---------------------------------------------------------------------------
__global__ void prep_w2_kernel(const float* __restrict__ kernels) {
    int n = blockIdx.x;
    int r = n >> 6, o = n & 63;
    for (int k = threadIdx.x; k < Kdim; k += blockDim.x) {
        int c = k & 31, pq = k >> 5, q = pq & 7, p = pq >> 3;
        int qr = (q + r) & 7;
        int base = p * 16384 + qr * 2048 + o * 32 + c;
        g_Wh[(size_t)n * Kdim + k] = __float2half_rn(kernels[base] + kernels[81920 + base]);
    }
}

__global__ void prep_bias_kernel(const float* __restrict__ bias) {
    int o = threadIdx.x;
    float s = 0.f;
#pragma unroll
    for (int pq = 0; pq < KRr * KAa; pq++) s += bias[pq * Oo + o];
    g_biasK[o] = 2.0f * s;
}

// ---------------------------------------------------------------------------
// Gather -> X fp16. One warp per m-row; each iteration covers 2 pq:
// lanes 0-15 -> pq=2j, lanes 16-31 -> pq=2j+1; each lane does 2 channels.
// ---------------------------------------------------------------------------
__global__ void gather_kernel(const float* __restrict__ signal,
                              const float* __restrict__ bary) {
    int m = blockIdx.x * 8 + (threadIdx.x >> 5);
    if (m >= Mdim) return;
    const int lane = threadIdx.x & 31;
    const int half = lane >> 4;
    const int cl   = (lane & 15) * 2;

    const int b = m / Nn;
    const int n = m - b * Nn;
    const float* sb = signal + (size_t)b * (Nn * Cc);
    const float* bm = bary + (size_t)(b * Nn + n) * (KRr * KAa * 6);

    uint32_t* xh = (uint32_t*)(g_Xh + (size_t)m * Kdim);

#pragma unroll 4
    for (int jp = 0; jp < KRr * KAa / 2; jp++) {
        const int pq = 2 * jp + half;
        const float* bb = bm + pq * 6;
        float ax = 0.f, ay = 0.f;
#pragma unroll
        for (int v = 0; v < 3; v++) {
            int   idx = (int)bb[2 * v];
            float w   = bb[2 * v + 1];
            float2 s = *(const float2*)&sb[(size_t)idx * Cc + cl];
            ax = fmaf(w, s.x, ax);
            ay = fmaf(w, s.y, ay);
        }
        __half2 hv = __halves2half2(__float2half_rn(ax), __float2half_rn(ay));
        xh[(pq * Cc + cl) >> 1] = *(const uint32_t*)&hv;
    }
}

// ---------------------------------------------------------------------------
// HMMA GEMM: Y = X[Mpad x 1280] * Wh^T -> [Mpad x 512]
// CTA 128x128, 8 warps (4m x 2n), warp tile 32x64, single fp16 mma pass.
// 3-stage cp.async ring, one __syncthreads per chunk. 2 CTAs/SM.
// ---------------------------------------------------------------------------
__global__ void __launch_bounds__(256, 2)
gemm_mma_kernel(float* __restrict__ out) {
    extern __shared__ __align__(1024) char smem[];
    const uint32_t sb0 = smem_u32(smem);
    const int tid  = threadIdx.x;
    const int wid  = tid >> 5;
    const int lane = tid & 31;
    const int wm = wid & 3;          // m quadrant (32 rows)
    const int wn = wid >> 2;         // n half (64 cols)

    const int j0 = blockIdx.x * TILE_N;   // n-split fastest -> A-tile L2 reuse
    const int m0 = blockIdx.y * TILE_M;

    // per-thread load slots
    const int l_row = tid >> 3;
    const int l_seg = tid & 7;
    const uint32_t l_doff = l_row * 128 + ((l_seg ^ (l_row & 7)) << 4);
    const size_t a_g = (size_t)(m0 + l_row) * Kdim + l_seg * 8;
    const size_t b_g = (size_t)(j0 + l_row) * Kdim + l_seg * 8;

    auto load_stage = [&](int c) {
        const int k0 = c * KCHUNK;
        const uint32_t sb = sb0 + (c % NSTAGE) * STAGE_BYTES;
#pragma unroll
        for (int i = 0; i < 4; i++) {
            uint32_t d = sb + l_doff + i * (32 * 128);
            cp16(d,         g_Xh + a_g + (size_t)(i * 32) * Kdim + k0);
            cp16(d + B_OFF, g_Wh + b_g + (size_t)(i * 32) * Kdim + k0);
        }
        asm volatile("cp.async.commit_group;" ::: "memory");
    };

    float acc[2][8][4];
#pragma unroll
    for (int mt = 0; mt < 2; mt++)
#pragma unroll
        for (int nt = 0; nt < 8; nt++)
#pragma unroll
            for (int i = 0; i < 4; i++) acc[mt][nt][i] = 0.f;

    // warp-constant ldsm base addresses (swizzle folded in; inner loop XORs ks<<5)
    const int sel = lane >> 4;
    uint32_t a_base[2], b_base[4];
#pragma unroll
    for (int mt = 0; mt < 2; mt++) {
        int r = wm * 32 + (lane & 15) + mt * 16;
        a_base[mt] = r * 128 + (((sel ^ r) & 7) << 4);
    }
#pragma unroll
    for (int bt = 0; bt < 4; bt++) {
        int r = wn * 64 + (lane & 15) + bt * 16;
        b_base[bt] = B_OFF + r * 128 + (((sel ^ r) & 7) << 4);
    }

    load_stage(0);
    load_stage(1);

    for (int c = 0; c < NCHUNK; c++) {
        if (c + 1 < NCHUNK) asm volatile("cp.async.wait_group 1;" ::: "memory");
        else                asm volatile("cp.async.wait_group 0;" ::: "memory");
        __syncthreads();
        if (c + 2 < NCHUNK) load_stage(c + 2);   // buffer (c+2)%3 was consumed at c-1

        const uint32_t sb = sb0 + (c % NSTAGE) * STAGE_BYTES;

#pragma unroll
        for (int ks = 0; ks < 4; ks++) {
            const uint32_t xv = ks << 5;
            uint32_t ah[2][4];
#pragma unroll
            for (int mt = 0; mt < 2; mt++)
                ldsm_x4((sb + a_base[mt]) ^ xv, ah[mt][0], ah[mt][1], ah[mt][2], ah[mt][3]);
            uint32_t bh[8][2];
#pragma unroll
            for (int bt = 0; bt < 4; bt++) {
                uint32_t r0, r1, r2, r3;
                ldsm_x4((sb + b_base[bt]) ^ xv, r0, r1, r2, r3);
                bh[2 * bt][0] = r0; bh[2 * bt][1] = r2;
                bh[2 * bt + 1][0] = r1; bh[2 * bt + 1][1] = r3;
            }
#pragma unroll
            for (int mt = 0; mt < 2; mt++)
#pragma unroll
                for (int nt = 0; nt < 8; nt++)
                    mma16816(acc[mt][nt], ah[mt], bh[nt][0], bh[nt][1]);
        }
    }

    // ---- epilogue
    const int r_out = (j0 + wn * 64) >> 6;
    const int ob = (lane & 3) * 2;
    float2 bias2[8];
#pragma unroll
    for (int nt = 0; nt < 8; nt++) {
        bias2[nt].x = g_biasK[nt * 8 + ob];
        bias2[nt].y = g_biasK[nt * 8 + ob + 1];
    }

#pragma unroll
    for (int mt = 0; mt < 2; mt++) {
#pragma unroll
        for (int half = 0; half < 2; half++) {
            int m = m0 + wm * 32 + mt * 16 + (lane >> 2) + half * 8;
            if (m >= Mdim) continue;
            int b = m / Nn;
            int n = m - b * Nn;
            float* op = out + (size_t)b * ((size_t)KAa * Nn * Oo)
                            + (size_t)r_out * ((size_t)Nn * Oo) + (size_t)n * Oo;
#pragma unroll
            for (int nt = 0; nt < 8; nt++) {
                float2 v;
                v.x = acc[mt][nt][half * 2 + 0] + bias2[nt].x;
                v.y = acc[mt][nt][half * 2 + 1] + bias2[nt].y;
                *(float2*)&op[nt * 8 + ob] = v;
            }
        }
    }
}

// ---------------------------------------------------------------------------
extern "C" void kernel_launch(void* const* d_in, const int* in_sizes, int n_in,
                              void* d_out, int out_size) {
    const float* signal  = (const float*)d_in[0];
    const float* bary    = (const float*)d_in[1];
    const float* kernels = (const float*)d_in[2];
    const float* bias    = (const float*)d_in[3];
    float* out = (float*)d_out;

    prep_w2_kernel<<<Ndim, 256>>>(kernels);
    prep_bias_kernel<<<1, Oo>>>(bias);

    gather_kernel<<<(Mdim + 7) / 8, 256>>>(signal, bary);

    {
        static int smem_set = 0;
        if (!smem_set) {
            cudaFuncSetAttribute(gemm_mma_kernel,
                                 cudaFuncAttributeMaxDynamicSharedMemorySize, GEMM_SMEM);
            smem_set = 1;
        }
        dim3 grid(Ndim / TILE_N, Mpad / TILE_M);   // (4, 313)
        gemm_mma_kernel<<<grid, 256, GEMM_SMEM>>>(out);
    }
}

// round 6
// speedup vs baseline: 6.9735x; 1.0003x over previous
#include <cuda_runtime.h>
#include <cuda_fp16.h>
#include <cstdint>

// ---------------- problem constants ----------------
#define Nn   10000
#define KRr  5
#define KAa  8
#define Cc   32
#define Oo   64

#define Mdim 40000            // B*N
#define Kdim 1280             // KR*KA*C
#define Ndim 512              // KA(rot)*O
#define Mpad 40064            // 313 * 128

// ---------------- GEMM tiling ----------------
#define TILE_M 128
#define TILE_N 128
#define KCHUNK 64                  // fp16 per K chunk (128 B per row)
#define NCHUNK (Kdim / KCHUNK)     // 20
#define B_OFF 16384
#define STAGE_BYTES 32768
#define NSTAGE 3
#define GEMM_SMEM (NSTAGE * STAGE_BYTES)   // 98304 -> 2 CTAs/SM

// ---------------- device scratch ----------------
__device__ __half g_Xh[(size_t)Mpad * Kdim];      // 102.6 MB
__device__ __half g_Wh[(size_t)Ndim * Kdim];      // W2^T fp16 [n][k]
__device__ __half g_Sh[(size_t)4 * Nn * Cc];      // signal fp16 (2.56 MB, L2-hot)
__device__ float  g_biasK[Oo];

// ---------------- helpers ----------------
__device__ __forceinline__ uint32_t smem_u32(const void* p) {
    uint32_t a;
    asm("{ .reg .u64 t; cvta.to.shared.u64 t, %1; cvt.u32.u64 %0, t; }" : "=r"(a) : "l"(p));
    return a;
}
__device__ __forceinline__ void cp16(uint32_t dst, const void* src) {
    asm volatile("cp.async.cg.shared.global [%0], [%1], 16;" :: "r"(dst), "l"(src));
}
__device__ __forceinline__ void ldsm_x4(uint32_t addr, uint32_t& r0, uint32_t& r1,
                                        uint32_t& r2, uint32_t& r3) {
    asm volatile("ldmatrix.sync.aligned.m8n8.x4.shared.b16 {%0,%1,%2,%3}, [%4];"
                 : "=r"(r0), "=r"(r1), "=r"(r2), "=r"(r3) : "r"(addr));
}
__device__ __forceinline__ void mma16816(float* c, const uint32_t* a,
                                         uint32_t b0, uint32_t b1) {
    asm volatile(
        "mma.sync.aligned.m16n8k16.row.col.f32.f16.f16.f32 "
        "{%0,%1,%2,%3}, {%4,%5,%6,%7}, {%8,%9}, {%0,%1,%2,%3};"
        : "+f"(c[0]), "+f"(c[1]), "+f"(c[2]), "+f"(c[3])
        : "r"(a[0]), "r"(a[1]), "r"(a[2]), "r"(a[3]), "r"(b0), "r"(b1));
}

// ---------------------------------------------------------------------------
// Signal -> fp16 (vectorized)
// ---------------------------------------------------------------------------
__global__ void conv_signal_kernel(const float* __restrict__ signal) {
    int i = blockIdx.x * blockDim.x + threadIdx.x;           // float4 index
    if (i >= (4 * Nn * Cc) / 4) return;
    float4 v = ((const float4*)signal)[i];
    __half2 h0 = __halves2half2(__float2half_rn(v.x), __float2half_rn(v.y));
    __half2 h1 = __halves2half2(__float2half_rn(v.z), __float2half_rn(v.w));
    ((__half2*)g_Sh)[2 * i]     = h0;
    ((__half2*)g_Sh)[2 * i + 1] = h1;
}

// ---------------------------------------------------------------------------
// Prep W2^T (fp16): Wh[n=r*64+o][k=(p*8+q)*32+c] = sum_g kernels[g,p,(q+r)&7,o,c]
// ---------------------------------------------------------------------------
__global__ void prep_w2_kernel(const float* __restrict__ kernels) {
    int n = blockIdx.x;
    int r = n >> 6, o = n & 63;
    for (int k = threadIdx.x; k < Kdim; k += blockDim.x) {
        int c = k & 31, pq = k >> 5, q = pq & 7, p = pq >> 3;
        int qr = (q + r) & 7;
        int base = p * 16384 + qr * 2048 + o * 32 + c;
        g_Wh[(size_t)n * Kdim + k] = __float2half_rn(kernels[base] + kernels[81920 + base]);
    }
}

__global__ void prep_bias_kernel(const float* __restrict__ bias) {
    int o = threadIdx.x;
    float s = 0.f;
#pragma unroll
    for (int pq = 0; pq < KRr * KAa; pq++) s += bias[pq * Oo + o];
    g_biasK[o] = 2.0f * s;
}

// ---------------------------------------------------------------------------
// Gather -> X fp16, reading fp16 signal (halves L2 traffic).
// One warp per m-row; lanes 0-15 -> pq=2j, lanes 16-31 -> pq=2j+1; 2 ch/lane.
// ---------------------------------------------------------------------------
__global__ void gather_kernel(const float* __restrict__ bary) {
    int m = blockIdx.x * 8 + (threadIdx.x >> 5);
    if (m >= Mdim) return;
    const int lane = threadIdx.x & 31;
    const int half = lane >> 4;
    const int cl   = (lane & 15) * 2;

    const int b = m / Nn;
    const int n = m - b * Nn;
    const __half2* sb = (const __half2*)(g_Sh + (size_t)b * (Nn * Cc));
    const float* bm = bary + (size_t)(b * Nn + n) * (KRr * KAa * 6);

    uint32_t* xh = (uint32_t*)(g_Xh + (size_t)m * Kdim);

#pragma unroll 4
    for (int jp = 0; jp < KRr * KAa / 2; jp++) {
        const int pq = 2 * jp + half;
        const float* bb = bm + pq * 6;
        float ax = 0.f, ay = 0.f;
#pragma unroll
        for (int v = 0; v < 3; v++) {
            int   idx = (int)bb[2 * v];
            float w   = bb[2 * v + 1];
            float2 s = __half22float2(sb[(idx * Cc + cl) >> 1]);
            ax = fmaf(w, s.x, ax);
            ay = fmaf(w, s.y, ay);
        }
        __half2 hv = __halves2half2(__float2half_rn(ax), __float2half_rn(ay));
        xh[(pq * Cc + cl) >> 1] = *(const uint32_t*)&hv;
    }
}

// ---------------------------------------------------------------------------
// HMMA GEMM: Y = X[Mpad x 1280] * Wh^T -> [Mpad x 512]
// CTA 128x128, 8 warps (4m x 2n), warp tile 32x64, fp16 mma.
// 3-stage cp.async ring + in-register fragment double-buffering.
// ---------------------------------------------------------------------------
__global__ void __launch_bounds__(256, 2)
gemm_mma_kernel(float* __restrict__ out) {
    extern __shared__ __align__(1024) char smem[];
    const uint32_t sb0 = smem_u32(smem);
    const int tid  = threadIdx.x;
    const int wid  = tid >> 5;
    const int lane = tid & 31;
    const int wm = wid & 3;
    const int wn = wid >> 2;

    const int j0 = blockIdx.x * TILE_N;
    const int m0 = blockIdx.y * TILE_M;

    // per-thread load slots (pointers precomputed once)
    const int l_row = tid >> 3;
    const int l_seg = tid & 7;
    const uint32_t l_doff = l_row * 128 + ((l_seg ^ (l_row & 7)) << 4);
    const __half* aptr = g_Xh + (size_t)(m0 + l_row) * Kdim + l_seg * 8;
    const __half* bptr = g_Wh + (size_t)(j0 + l_row) * Kdim + l_seg * 8;

    auto load_stage = [&](int c) {
        const uint32_t sb = sb0 + (c % NSTAGE) * STAGE_BYTES;
        const __half* a = aptr + c * KCHUNK;
        const __half* b = bptr + c * KCHUNK;
#pragma unroll
        for (int i = 0; i < 4; i++) {
            uint32_t d = sb + l_doff + i * (32 * 128);
            cp16(d,         a + (size_t)(i * 32) * Kdim);
            cp16(d + B_OFF, b + (size_t)(i * 32) * Kdim);
        }
        asm volatile("cp.async.commit_group;" ::: "memory");
    };

    float acc[2][8][4];
#pragma unroll
    for (int mt = 0; mt < 2; mt++)
#pragma unroll
        for (int nt = 0; nt < 8; nt++)
#pragma unroll
            for (int i = 0; i < 4; i++) acc[mt][nt][i] = 0.f;

    const int sel = lane >> 4;
    uint32_t a_base[2], b_base[4];
#pragma unroll
    for (int mt = 0; mt < 2; mt++) {
        int r = wm * 32 + (lane & 15) + mt * 16;
        a_base[mt] = r * 128 + (((sel ^ r) & 7) << 4);
    }
#pragma unroll
    for (int bt = 0; bt < 4; bt++) {
        int r = wn * 64 + (lane & 15) + bt * 16;
        b_base[bt] = B_OFF + r * 128 + (((sel ^ r) & 7) << 4);
    }

    // fragment loader for one ks
    uint32_t ah[2][2][4], bh[2][8][2];
    auto load_frags = [&](uint32_t sb, int ks, int buf) {
        const uint32_t xv = ks << 5;
#pragma unroll
        for (int mt = 0; mt < 2; mt++)
            ldsm_x4((sb + a_base[mt]) ^ xv,
                    ah[buf][mt][0], ah[buf][mt][1], ah[buf][mt][2], ah[buf][mt][3]);
#pragma unroll
        for (int bt = 0; bt < 4; bt++) {
            uint32_t r0, r1, r2, r3;
            ldsm_x4((sb + b_base[bt]) ^ xv, r0, r1, r2, r3);
            bh[buf][2 * bt][0] = r0; bh[buf][2 * bt][1] = r2;
            bh[buf][2 * bt + 1][0] = r1; bh[buf][2 * bt + 1][1] = r3;
        }
    };

    load_stage(0);
    load_stage(1);

    for (int c = 0; c < NCHUNK; c++) {
        if (c + 1 < NCHUNK) asm volatile("cp.async.wait_group 1;" ::: "memory");
        else                asm volatile("cp.async.wait_group 0;" ::: "memory");
        __syncthreads();
        if (c + 2 < NCHUNK) load_stage(c + 2);

        const uint32_t sb = sb0 + (c % NSTAGE) * STAGE_BYTES;

        load_frags(sb, 0, 0);
#pragma unroll
        for (int ks = 0; ks < 4; ks++) {
            const int cur = ks & 1;
            if (ks < 3) load_frags(sb, ks + 1, cur ^ 1);
#pragma unroll
            for (int mt = 0; mt < 2; mt++)
#pragma unroll
                for (int nt = 0; nt < 8; nt++)
                    mma16816(acc[mt][nt], ah[cur][mt], bh[cur][nt][0], bh[cur][nt][1]);
        }
    }

    // ---- epilogue
    const int r_out = (j0 + wn * 64) >> 6;
    const int ob = (lane & 3) * 2;
    float2 bias2[8];
#pragma unroll
    for (int nt = 0; nt < 8; nt++) {
        bias2[nt].x = g_biasK[nt * 8 + ob];
        bias2[nt].y = g_biasK[nt * 8 + ob + 1];
    }

#pragma unroll
    for (int mt = 0; mt < 2; mt++) {
#pragma unroll
        for (int half = 0; half < 2; half++) {
            int m = m0 + wm * 32 + mt * 16 + (lane >> 2) + half * 8;
            if (m >= Mdim) continue;
            int b = m / Nn;
            int n = m - b * Nn;
            float* op = out + (size_t)b * ((size_t)KAa * Nn * Oo)
                            + (size_t)r_out * ((size_t)Nn * Oo) + (size_t)n * Oo;
#pragma unroll
            for (int nt = 0; nt < 8; nt++) {
                float2 v;
                v.x = acc[mt][nt][half * 2 + 0] + bias2[nt].x;
                v.y = acc[mt][nt][half * 2 + 1] + bias2[nt].y;
                *(float2*)&op[nt * 8 + ob] = v;
            }
        }
    }
}

// ---------------------------------------------------------------------------
extern "C" void kernel_launch(void* const* d_in, const int* in_sizes, int n_in,
                              void* d_out, int out_size) {
    const float* signal  = (const float*)d_in[0];
    const float* bary    = (const float*)d_in[1];
    const float* kernels = (const float*)d_in[2];
    const float* bias    = (const float*)d_in[3];
    float* out = (float*)d_out;

    conv_signal_kernel<<<(4 * Nn * Cc / 4 + 255) / 256, 256>>>(signal);
    prep_w2_kernel<<<Ndim, 256>>>(kernels);
    prep_bias_kernel<<<1, Oo>>>(bias);

    gather_kernel<<<(Mdim + 7) / 8, 256>>>(bary);

    {
        static int smem_set = 0;
        if (!smem_set) {
            cudaFuncSetAttribute(gemm_mma_kernel,
                                 cudaFuncAttributeMaxDynamicSharedMemorySize, GEMM_SMEM);
            smem_set = 1;
        }
        dim3 grid(Ndim / TILE_N, Mpad / TILE_M);   // (4, 313)
        gemm_mma_kernel<<<grid, 256, GEMM_SMEM>>>(out);
    }
}

// round 7
// speedup vs baseline: 11.0215x; 1.5805x over previous
#include <cuda_runtime.h>
#include <cuda_fp16.h>
#include <cstdint>

// ---------------- problem constants ----------------
#define Nn   10000
#define KRr  5
#define KAa  8
#define Cc   32
#define Oo   64

#define Mdim 40000            // B*N
#define Kdim 1280             // KR*KA*C  (X-hat row width)
#define Mpad 40064            // 313 * 128

// ---------------- frequency-block GEMM tiling ----------------
#define KF   320                   // K per freq block
#define NF   128                   // N per freq block
#define NBLK 4                     // {f0|f4}, f1, f2, f3
#define KCHUNK 64                  // fp16 per K chunk (128 B per row)
#define NCHUNK_F (KF / KCHUNK)     // 5
#define B_OFF 16384
#define STAGE_BYTES 32768
#define NSTAGE 3
#define GEMM_SMEM (NSTAGE * STAGE_BYTES)   // 98304 -> 2 CTAs/SM

#define SQH 0.70710678118654752f

// ---------------- device scratch ----------------
__device__ __half g_Xh[(size_t)Mpad * Kdim];        // X-hat fp16 (freq layout)
__device__ __half g_Wb[(size_t)NBLK * NF * KF];     // W-hat blocks [4][128][320]
__device__ __half g_Sh[(size_t)4 * Nn * Cc];        // signal fp16
__device__ float  g_Y[(size_t)Mpad * 512];          // freq-domain GEMM output
__device__ float  g_biasK[Oo];

// ---------------- helpers ----------------
__device__ __forceinline__ uint32_t smem_u32(const void* p) {
    uint32_t a;
    asm("{ .reg .u64 t; cvta.to.shared.u64 t, %1; cvt.u32.u64 %0, t; }" : "=r"(a) : "l"(p));
    return a;
}
__device__ __forceinline__ void cp16(uint32_t dst, const void* src) {
    asm volatile("cp.async.cg.shared.global [%0], [%1], 16;" :: "r"(dst), "l"(src));
}
__device__ __forceinline__ void ldsm_x4(uint32_t addr, uint32_t& r0, uint32_t& r1,
                                        uint32_t& r2, uint32_t& r3) {
    asm volatile("ldmatrix.sync.aligned.m8n8.x4.shared.b16 {%0,%1,%2,%3}, [%4];"
                 : "=r"(r0), "=r"(r1), "=r"(r2), "=r"(r3) : "r"(addr));
}
__device__ __forceinline__ void mma16816(float* c, const uint32_t* a,
                                         uint32_t b0, uint32_t b1) {
    asm volatile(
        "mma.sync.aligned.m16n8k16.row.col.f32.f16.f16.f32 "
        "{%0,%1,%2,%3}, {%4,%5,%6,%7}, {%8,%9}, {%0,%1,%2,%3};"
        : "+f"(c[0]), "+f"(c[1]), "+f"(c[2]), "+f"(c[3])
        : "r"(a[0]), "r"(a[1]), "r"(a[2]), "r"(a[3]), "r"(b0), "r"(b1));
}

// 8-point real DFT: x[0..7] -> {X0, X4, Re1, Im1, Re2, Im2, Re3, Im3}
// X_f = sum_q x_q * e^{-2*pi*i*f*q/8}
__device__ __forceinline__ void fft8(const float* x, float* o) {
    float p04 = x[0] + x[4], m04 = x[0] - x[4];
    float p26 = x[2] + x[6], m26 = x[2] - x[6];
    float pbd = x[1] + x[3], pfh = x[5] + x[7];
    float mbd = x[1] - x[3], mfh = x[5] - x[7];
    float sodd = pbd + pfh;
    float B1 = mbd - mfh;           // (b-d) - (f-h)
    float B2 = pfh - pbd;           // (f+h) - (b+d)
    o[0] = p04 + p26 + sodd;        // X0
    o[1] = p04 + p26 - sodd;        // X4
    o[2] = m04 + SQH * B1;          // Re1
    o[3] = -m26 + SQH * B2;         // Im1
    o[4] = p04 - p26;               // Re2
    o[5] = -(mbd + mfh);            // Im2
    o[6] = m04 - SQH * B1;          // Re3
    o[7] = m26 + SQH * B2;          // Im3
}

// ---------------------------------------------------------------------------
// Signal -> fp16
// ---------------------------------------------------------------------------
__global__ void conv_signal_kernel(const float* __restrict__ signal) {
    int i = blockIdx.x * blockDim.x + threadIdx.x;
    if (i >= (4 * Nn * Cc) / 4) return;
    float4 v = ((const float4*)signal)[i];
    __half2 h0 = __halves2half2(__float2half_rn(v.x), __float2half_rn(v.y));
    __half2 h1 = __halves2half2(__float2half_rn(v.z), __float2half_rn(v.w));
    ((__half2*)g_Sh)[2 * i]     = h0;
    ((__half2*)g_Sh)[2 * i + 1] = h1;
}

// ---------------------------------------------------------------------------
// Prep W-hat blocks. Row = g*128 + n', n' = h*64 + o; col k' in [0,320):
// half = k'>=160, (p,c) from k'%160.
//   g=0: h0,half0 -> sum_q Wsum ; h1,half1 -> sum_q (-1)^q Wsum ; else 0
//   g=f: Wr = sum Wsum*cos(pi f q/4), Wi = -sum Wsum*sin(pi f q/4)
//        h0: [Wr ; Wi]   h1: [Wi ; -Wr]
// ---------------------------------------------------------------------------
__global__ void prep_wb_kernel(const float* __restrict__ kernels) {
    const int row = blockIdx.x;            // 0..511
    const int g = row >> 7;
    const int np = row & 127;
    const int h = np >> 6, o = np & 63;
    const int kp = threadIdx.x;            // 0..319
    const int half = (kp >= 160) ? 1 : 0;
    const int kk = kp - 160 * half;
    const int p = kk >> 5, c = kk & 31;

    float wsum[8];
#pragma unroll
    for (int q = 0; q < 8; q++) {
        int base = p * 16384 + q * 2048 + o * 32 + c;
        wsum[q] = kernels[base] + kernels[81920 + base];
    }

    float val = 0.f;
    if (g == 0) {
        if (h == 0 && half == 0) {
#pragma unroll
            for (int q = 0; q < 8; q++) val += wsum[q];
        } else if (h == 1 && half == 1) {
#pragma unroll
            for (int q = 0; q < 8; q++) val += (q & 1) ? -wsum[q] : wsum[q];
        }
    } else {
        const float ct[8] = {1.f, SQH, 0.f, -SQH, -1.f, -SQH, 0.f, SQH};
        const float st[8] = {0.f, SQH, 1.f, SQH, 0.f, -SQH, -1.f, -SQH};
        float Wr = 0.f, Wi = 0.f;
#pragma unroll
        for (int q = 0; q < 8; q++) {
            int i = (g * q) & 7;
            Wr += wsum[q] * ct[i];
            Wi -= wsum[q] * st[i];
        }
        if (h == 0) val = half ? Wi : Wr;
        else        val = half ? -Wr : Wi;
    }
    g_Wb[(size_t)row * KF + kp] = __float2half_rn(val);
}

__global__ void prep_bias_kernel(const float* __restrict__ bias) {
    int o = threadIdx.x;
    float s = 0.f;
#pragma unroll
    for (int pq = 0; pq < KRr * KAa; pq++) s += bias[pq * Oo + o];
    g_biasK[o] = 2.0f * s;
}

// ---------------------------------------------------------------------------
// Gather + FFT over angular axis -> X-hat fp16.
// Warp handles 2 m-rows (half-warp each); lane covers a channel pair.
// X-hat row layout (1280 halfs): comp*160 + p*32 + c, comp order:
//   {X0, X4, Xr1, Xi1, Xr2, Xi2, Xr3, Xi3}
// ---------------------------------------------------------------------------
__global__ void gather_fft_kernel(const float* __restrict__ bary) {
    const int warp = blockIdx.x * 8 + (threadIdx.x >> 5);
    const int lane = threadIdx.x & 31;
    const int m = warp * 2 + (lane >> 4);
    if (m >= Mdim) return;
    const int cp = lane & 15;              // channel pair -> channels 2cp, 2cp+1

    const int b = m / Nn;
    const int n = m - b * Nn;
    const __half2* sb = (const __half2*)(g_Sh + (size_t)b * (Nn * Cc));
    const float* bm = bary + (size_t)(b * Nn + n) * (KRr * KAa * 6);

    uint32_t* xrow = (uint32_t*)(g_Xh + (size_t)m * Kdim);   // half2 units

#pragma unroll
    for (int p = 0; p < KRr; p++) {
        float xq[8], yq[8];
#pragma unroll
        for (int q = 0; q < 8; q++) {
            const float* bb = bm + (p * 8 + q) * 6;
            float ax = 0.f, ay = 0.f;
#pragma unroll
            for (int v = 0; v < 3; v++) {
                int   idx = (int)bb[2 * v];
                float w   = bb[2 * v + 1];
                float2 s = __half22float2(sb[idx * 16 + cp]);
                ax = fmaf(w, s.x, ax);
                ay = fmaf(w, s.y, ay);
            }
            xq[q] = ax; yq[q] = ay;
        }
        float ox[8], oy[8];
        fft8(xq, ox);
        fft8(yq, oy);
#pragma unroll
        for (int comp = 0; comp < 8; comp++) {
            __half2 hv = __halves2half2(__float2half_rn(ox[comp]),
                                        __float2half_rn(oy[comp]));
            xrow[comp * 80 + p * 16 + cp] = *(const uint32_t*)&hv;
        }
    }
}

// ---------------------------------------------------------------------------
// HMMA GEMM per freq block: Y[m][g*128 + n'] = X-hat[m][g*320 : +320] . Wb[g][n']
// grid (4 blocks, 313 m-tiles); CTA 128x128, K=320 in 5 chunks. fp32 out.
// ---------------------------------------------------------------------------
__global__ void __launch_bounds__(256, 2)
gemm_mma_kernel() {
    extern __shared__ __align__(1024) char smem[];
    const uint32_t sb0 = smem_u32(smem);
    const int tid  = threadIdx.x;
    const int wid  = tid >> 5;
    const int lane = tid & 31;
    const int wm = wid & 3;
    const int wn = wid >> 2;

    const int g  = blockIdx.x;            // freq block
    const int m0 = blockIdx.y * 128;

    const int l_row = tid >> 3;
    const int l_seg = tid & 7;
    const uint32_t l_doff = l_row * 128 + ((l_seg ^ (l_row & 7)) << 4);
    const __half* aptr = g_Xh + (size_t)(m0 + l_row) * Kdim + g * KF + l_seg * 8;
    const __half* bptr = g_Wb + (size_t)(g * NF + l_row) * KF + l_seg * 8;

    auto load_stage = [&](int c) {
        const uint32_t sb = sb0 + (c % NSTAGE) * STAGE_BYTES;
        const __half* a = aptr + c * KCHUNK;
        const __half* b = bptr + c * KCHUNK;
#pragma unroll
        for (int i = 0; i < 4; i++) {
            uint32_t d = sb + l_doff + i * (32 * 128);
            cp16(d,         a + (size_t)(i * 32) * Kdim);
            cp16(d + B_OFF, b + (size_t)(i * 32) * KF);
        }
        asm volatile("cp.async.commit_group;" ::: "memory");
    };

    float acc[2][8][4];
#pragma unroll
    for (int mt = 0; mt < 2; mt++)
#pragma unroll
        for (int nt = 0; nt < 8; nt++)
#pragma unroll
            for (int i = 0; i < 4; i++) acc[mt][nt][i] = 0.f;

    const int sel = lane >> 4;
    uint32_t a_base[2], b_base[4];
#pragma unroll
    for (int mt = 0; mt < 2; mt++) {
        int r = wm * 32 + (lane & 15) + mt * 16;
        a_base[mt] = r * 128 + (((sel ^ r) & 7) << 4);
    }
#pragma unroll
    for (int bt = 0; bt < 4; bt++) {
        int r = wn * 64 + (lane & 15) + bt * 16;
        b_base[bt] = B_OFF + r * 128 + (((sel ^ r) & 7) << 4);
    }

    load_stage(0);
    load_stage(1);

    for (int c = 0; c < NCHUNK_F; c++) {
        if (c + 1 < NCHUNK_F) asm volatile("cp.async.wait_group 1;" ::: "memory");
        else                  asm volatile("cp.async.wait_group 0;" ::: "memory");
        __syncthreads();
        if (c + 2 < NCHUNK_F) load_stage(c + 2);

        const uint32_t sb = sb0 + (c % NSTAGE) * STAGE_BYTES;

#pragma unroll
        for (int ks = 0; ks < 4; ks++) {
            const uint32_t xv = ks << 5;
            uint32_t ah[2][4];
#pragma unroll
            for (int mt = 0; mt < 2; mt++)
                ldsm_x4((sb + a_base[mt]) ^ xv, ah[mt][0], ah[mt][1], ah[mt][2], ah[mt][3]);
            uint32_t bh[8][2];
#pragma unroll
            for (int bt = 0; bt < 4; bt++) {
                uint32_t r0, r1, r2, r3;
                ldsm_x4((sb + b_base[bt]) ^ xv, r0, r1, r2, r3);
                bh[2 * bt][0] = r0; bh[2 * bt][1] = r2;
                bh[2 * bt + 1][0] = r1; bh[2 * bt + 1][1] = r3;
            }
#pragma unroll
            for (int mt = 0; mt < 2; mt++)
#pragma unroll
                for (int nt = 0; nt < 8; nt++)
                    mma16816(acc[mt][nt], ah[mt], bh[nt][0], bh[nt][1]);
        }
    }

    // epilogue: write Y block (fp32, no bias)
    const int ob = (lane & 3) * 2;
#pragma unroll
    for (int mt = 0; mt < 2; mt++) {
#pragma unroll
        for (int half = 0; half < 2; half++) {
            int m = m0 + wm * 32 + mt * 16 + (lane >> 2) + half * 8;
            float* yp = g_Y + (size_t)m * 512 + g * NF + wn * 64;
#pragma unroll
            for (int nt = 0; nt < 8; nt++) {
                float2 v;
                v.x = acc[mt][nt][half * 2 + 0];
                v.y = acc[mt][nt][half * 2 + 1];
                *(float2*)&yp[nt * 8 + ob] = v;
            }
        }
    }
}

// ---------------------------------------------------------------------------
// Combine: inverse twiddle over 8 freq components + bias, scatter to out.
// out[m,r,o] = 1/8*(Z0 + (-1)^r Z4) + 1/4*sum_f (c_fr*ReY_f - s_fr*ImY_f) + bias[o]
// Warp = one m-row; lane covers an o-pair.
// ---------------------------------------------------------------------------
__global__ void combine_kernel(float* __restrict__ out) {
    const int m = blockIdx.x * 8 + (threadIdx.x >> 5);
    if (m >= Mdim) return;
    const int lane = threadIdx.x & 31;

    const float2* y2 = (const float2*)(g_Y + (size_t)m * 512);
    float2 Z0 = y2[lane];
    float2 Z4 = y2[32 + lane];
    float2 R1 = y2[64 + lane];
    float2 I1 = y2[96 + lane];
    float2 R2 = y2[128 + lane];
    float2 I2 = y2[160 + lane];
    float2 R3 = y2[192 + lane];
    float2 I3 = y2[224 + lane];

    const float bx = g_biasK[2 * lane];
    const float by = g_biasK[2 * lane + 1];

    const int b = m / Nn;
    const int n = m - b * Nn;
    float* op = out + (size_t)b * ((size_t)KAa * Nn * Oo) + (size_t)n * Oo + 2 * lane;

    const float C1[8] = {1.f, SQH, 0.f, -SQH, -1.f, -SQH, 0.f, SQH};
    const float S1[8] = {0.f, SQH, 1.f, SQH, 0.f, -SQH, -1.f, -SQH};
    const float C2[8] = {1.f, 0.f, -1.f, 0.f, 1.f, 0.f, -1.f, 0.f};
    const float S2[8] = {0.f, 1.f, 0.f, -1.f, 0.f, 1.f, 0.f, -1.f};
    const float C3[8] = {1.f, -SQH, 0.f, SQH, -1.f, SQH, 0.f, -SQH};
    const float S3[8] = {0.f, SQH, -1.f, SQH, 0.f, -SQH, 1.f, -SQH};

#pragma unroll
    for (int r = 0; r < 8; r++) {
        float sg = (r & 1) ? -1.f : 1.f;
        float2 v;
        v.x = 0.125f * (Z0.x + sg * Z4.x)
            + 0.25f * (C1[r] * R1.x - S1[r] * I1.x
                     + C2[r] * R2.x - S2[r] * I2.x
                     + C3[r] * R3.x - S3[r] * I3.x) + bx;
        v.y = 0.125f * (Z0.y + sg * Z4.y)
            + 0.25f * (C1[r] * R1.y - S1[r] * I1.y
                     + C2[r] * R2.y - S2[r] * I2.y
                     + C3[r] * R3.y - S3[r] * I3.y) + by;
        *(float2*)&op[(size_t)r * (Nn * Oo)] = v;
    }
}

// ---------------------------------------------------------------------------
extern "C" void kernel_launch(void* const* d_in, const int* in_sizes, int n_in,
                              void* d_out, int out_size) {
    const float* signal  = (const float*)d_in[0];
    const float* bary    = (const float*)d_in[1];
    const float* kernels = (const float*)d_in[2];
    const float* bias    = (const float*)d_in[3];
    float* out = (float*)d_out;

    conv_signal_kernel<<<(4 * Nn * Cc / 4 + 255) / 256, 256>>>(signal);
    prep_wb_kernel<<<NBLK * NF, KF>>>(kernels);
    prep_bias_kernel<<<1, Oo>>>(bias);

    gather_fft_kernel<<<Mdim / 16, 256>>>(bary);

    {
        static int smem_set = 0;
        if (!smem_set) {
            cudaFuncSetAttribute(gemm_mma_kernel,
                                 cudaFuncAttributeMaxDynamicSharedMemorySize, GEMM_SMEM);
            smem_set = 1;
        }
        dim3 grid(NBLK, Mpad / 128);   // (4, 313)
        gemm_mma_kernel<<<grid, 256, GEMM_SMEM>>>();
    }

    combine_kernel<<<Mdim / 8, 256>>>(out);
}

// round 8
// speedup vs baseline: 11.0798x; 1.0053x over previous
#include <cuda_runtime.h>
#include <cuda_fp16.h>
#include <cstdint>

// ---------------- problem constants ----------------
#define Nn   10000
#define KRr  5
#define KAa  8
#define Cc   32
#define Oo   64

#define Mdim 40000            // B*N
#define Kdim 1280             // KR*KA*C  (X-hat row width)
#define Mpad 40064            // 313 * 128

// ---------------- frequency-block GEMM tiling ----------------
#define KF   320                   // K per freq block
#define NF   128                   // N per freq block
#define NBLK 4                     // {f0|f4}, f1, f2, f3
#define KCHUNK 64                  // fp16 per K chunk (128 B per row)
#define NCHUNK_F (KF / KCHUNK)     // 5
#define B_OFF 16384
#define STAGE_BYTES 32768
#define NSTAGE 3
#define GEMM_SMEM (NSTAGE * STAGE_BYTES)   // 98304 -> 2 CTAs/SM

#define SQH 0.70710678118654752f

// ---------------- device scratch ----------------
__device__ __half g_Xh[(size_t)Mpad * Kdim];        // X-hat fp16 (freq layout)
__device__ __half g_Wb[(size_t)NBLK * NF * KF];     // W-hat blocks [4][128][320]
__device__ __half g_Sh[(size_t)4 * Nn * Cc];        // signal fp16
__device__ float  g_Y[(size_t)Mpad * 512];          // freq-domain GEMM output
__device__ float  g_biasK[Oo];

// ---------------- helpers ----------------
__device__ __forceinline__ uint32_t smem_u32(const void* p) {
    uint32_t a;
    asm("{ .reg .u64 t; cvta.to.shared.u64 t, %1; cvt.u32.u64 %0, t; }" : "=r"(a) : "l"(p));
    return a;
}
__device__ __forceinline__ void cp16(uint32_t dst, const void* src) {
    asm volatile("cp.async.cg.shared.global [%0], [%1], 16;" :: "r"(dst), "l"(src));
}
__device__ __forceinline__ void ldsm_x4(uint32_t addr, uint32_t& r0, uint32_t& r1,
                                        uint32_t& r2, uint32_t& r3) {
    asm volatile("ldmatrix.sync.aligned.m8n8.x4.shared.b16 {%0,%1,%2,%3}, [%4];"
                 : "=r"(r0), "=r"(r1), "=r"(r2), "=r"(r3) : "r"(addr));
}
__device__ __forceinline__ void mma16816(float* c, const uint32_t* a,
                                         uint32_t b0, uint32_t b1) {
    asm volatile(
        "mma.sync.aligned.m16n8k16.row.col.f32.f16.f16.f32 "
        "{%0,%1,%2,%3}, {%4,%5,%6,%7}, {%8,%9}, {%0,%1,%2,%3};"
        : "+f"(c[0]), "+f"(c[1]), "+f"(c[2]), "+f"(c[3])
        : "r"(a[0]), "r"(a[1]), "r"(a[2]), "r"(a[3]), "r"(b0), "r"(b1));
}

// 8-point real DFT: x[0..7] -> {X0, X4, Re1, Im1, Re2, Im2, Re3, Im3}
__device__ __forceinline__ void fft8(const float* x, float* o) {
    float p04 = x[0] + x[4], m04 = x[0] - x[4];
    float p26 = x[2] + x[6], m26 = x[2] - x[6];
    float pbd = x[1] + x[3], pfh = x[5] + x[7];
    float mbd = x[1] - x[3], mfh = x[5] - x[7];
    float sodd = pbd + pfh;
    float B1 = mbd - mfh;
    float B2 = pfh - pbd;
    o[0] = p04 + p26 + sodd;
    o[1] = p04 + p26 - sodd;
    o[2] = m04 + SQH * B1;
    o[3] = -m26 + SQH * B2;
    o[4] = p04 - p26;
    o[5] = -(mbd + mfh);
    o[6] = m04 - SQH * B1;
    o[7] = m26 + SQH * B2;
}

// ---------------------------------------------------------------------------
// Signal -> fp16
// ---------------------------------------------------------------------------
__global__ void conv_signal_kernel(const float* __restrict__ signal) {
    int i = blockIdx.x * blockDim.x + threadIdx.x;
    if (i >= (4 * Nn * Cc) / 4) return;
    float4 v = ((const float4*)signal)[i];
    __half2 h0 = __halves2half2(__float2half_rn(v.x), __float2half_rn(v.y));
    __half2 h1 = __halves2half2(__float2half_rn(v.z), __float2half_rn(v.w));
    ((__half2*)g_Sh)[2 * i]     = h0;
    ((__half2*)g_Sh)[2 * i + 1] = h1;
}

// ---------------------------------------------------------------------------
// Prep W-hat blocks (unchanged from R7)
// ---------------------------------------------------------------------------
__global__ void prep_wb_kernel(const float* __restrict__ kernels) {
    const int row = blockIdx.x;            // 0..511
    const int g = row >> 7;
    const int np = row & 127;
    const int h = np >> 6, o = np & 63;
    const int kp = threadIdx.x;            // 0..319
    const int half = (kp >= 160) ? 1 : 0;
    const int kk = kp - 160 * half;
    const int p = kk >> 5, c = kk & 31;

    float wsum[8];
#pragma unroll
    for (int q = 0; q < 8; q++) {
        int base = p * 16384 + q * 2048 + o * 32 + c;
        wsum[q] = kernels[base] + kernels[81920 + base];
    }

    float val = 0.f;
    if (g == 0) {
        if (h == 0 && half == 0) {
#pragma unroll
            for (int q = 0; q < 8; q++) val += wsum[q];
        } else if (h == 1 && half == 1) {
#pragma unroll
            for (int q = 0; q < 8; q++) val += (q & 1) ? -wsum[q] : wsum[q];
        }
    } else {
        const float ct[8] = {1.f, SQH, 0.f, -SQH, -1.f, -SQH, 0.f, SQH};
        const float st[8] = {0.f, SQH, 1.f, SQH, 0.f, -SQH, -1.f, -SQH};
        float Wr = 0.f, Wi = 0.f;
#pragma unroll
        for (int q = 0; q < 8; q++) {
            int i = (g * q) & 7;
            Wr += wsum[q] * ct[i];
            Wi -= wsum[q] * st[i];
        }
        if (h == 0) val = half ? Wi : Wr;
        else        val = half ? -Wr : Wi;
    }
    g_Wb[(size_t)row * KF + kp] = __float2half_rn(val);
}

__global__ void prep_bias_kernel(const float* __restrict__ bias) {
    int o = threadIdx.x;
    float s = 0.f;
#pragma unroll
    for (int pq = 0; pq < KRr * KAa; pq++) s += bias[pq * Oo + o];
    g_biasK[o] = 2.0f * s;
}

// ---------------------------------------------------------------------------
// Gather + FFT -> X-hat fp16.  Warp covers 4 m-rows: 8-lane group per m,
// 4 channels per lane. Loads: bary float2 (group-broadcast), signal uint2.
// Stores: uint2 per (p,comp).
// X-hat row layout (halfs): comp*160 + p*32 + c
// ---------------------------------------------------------------------------
__global__ void gather_fft_kernel(const float* __restrict__ bary) {
    const int warp = blockIdx.x * 8 + (threadIdx.x >> 5);
    const int lane = threadIdx.x & 31;
    const int grp  = lane >> 3;          // m within warp
    const int sub  = lane & 7;           // channel quad: c0 = sub*4
    const int m = warp * 4 + grp;
    if (m >= Mdim) return;

    const int b = m / Nn;
    const int n = m - b * Nn;
    const uint2*  sb = (const uint2*)(g_Sh + (size_t)b * (Nn * Cc));
    const float2* bm = (const float2*)(bary + (size_t)(b * Nn + n) * 240);
    uint2* xrow = (uint2*)(g_Xh + (size_t)m * Kdim);

#pragma unroll
    for (int p = 0; p < KRr; p++) {
        float acc[8][4];
#pragma unroll
        for (int q = 0; q < 8; q++) {
            const float2* bb = bm + (p * 8 + q) * 3;
            float a0 = 0.f, a1 = 0.f, a2 = 0.f, a3 = 0.f;
#pragma unroll
            for (int v = 0; v < 3; v++) {
                float2 iw = bb[v];
                int idx = (int)iw.x;
                uint2 s = sb[idx * 8 + sub];
                float2 f0 = __half22float2(*(const __half2*)&s.x);
                float2 f1 = __half22float2(*(const __half2*)&s.y);
                a0 = fmaf(iw.y, f0.x, a0);
                a1 = fmaf(iw.y, f0.y, a1);
                a2 = fmaf(iw.y, f1.x, a2);
                a3 = fmaf(iw.y, f1.y, a3);
            }
            acc[q][0] = a0; acc[q][1] = a1; acc[q][2] = a2; acc[q][3] = a3;
        }
        float o[4][8];
#pragma unroll
        for (int j = 0; j < 4; j++) {
            float in[8];
#pragma unroll
            for (int q = 0; q < 8; q++) in[q] = acc[q][j];
            fft8(in, o[j]);
        }
#pragma unroll
        for (int comp = 0; comp < 8; comp++) {
            __half2 h0 = __halves2half2(__float2half_rn(o[0][comp]),
                                        __float2half_rn(o[1][comp]));
            __half2 h1 = __halves2half2(__float2half_rn(o[2][comp]),
                                        __float2half_rn(o[3][comp]));
            uint2 v;
            v.x = *(const uint32_t*)&h0;
            v.y = *(const uint32_t*)&h1;
            xrow[comp * 40 + p * 8 + sub] = v;
        }
    }
}

// ---------------------------------------------------------------------------
// HMMA GEMM per freq block (unchanged from R7)
// ---------------------------------------------------------------------------
__global__ void __launch_bounds__(256, 2)
gemm_mma_kernel() {
    extern __shared__ __align__(1024) char smem[];
    const uint32_t sb0 = smem_u32(smem);
    const int tid  = threadIdx.x;
    const int wid  = tid >> 5;
    const int lane = tid & 31;
    const int wm = wid & 3;
    const int wn = wid >> 2;

    const int g  = blockIdx.x;
    const int m0 = blockIdx.y * 128;

    const int l_row = tid >> 3;
    const int l_seg = tid & 7;
    const uint32_t l_doff = l_row * 128 + ((l_seg ^ (l_row & 7)) << 4);
    const __half* aptr = g_Xh + (size_t)(m0 + l_row) * Kdim + g * KF + l_seg * 8;
    const __half* bptr = g_Wb + (size_t)(g * NF + l_row) * KF + l_seg * 8;

    auto load_stage = [&](int c) {
        const uint32_t sb = sb0 + (c % NSTAGE) * STAGE_BYTES;
        const __half* a = aptr + c * KCHUNK;
        const __half* b = bptr + c * KCHUNK;
#pragma unroll
        for (int i = 0; i < 4; i++) {
            uint32_t d = sb + l_doff + i * (32 * 128);
            cp16(d,         a + (size_t)(i * 32) * Kdim);
            cp16(d + B_OFF, b + (size_t)(i * 32) * KF);
        }
        asm volatile("cp.async.commit_group;" ::: "memory");
    };

    float acc[2][8][4];
#pragma unroll
    for (int mt = 0; mt < 2; mt++)
#pragma unroll
        for (int nt = 0; nt < 8; nt++)
#pragma unroll
            for (int i = 0; i < 4; i++) acc[mt][nt][i] = 0.f;

    const int sel = lane >> 4;
    uint32_t a_base[2], b_base[4];
#pragma unroll
    for (int mt = 0; mt < 2; mt++) {
        int r = wm * 32 + (lane & 15) + mt * 16;
        a_base[mt] = r * 128 + (((sel ^ r) & 7) << 4);
    }
#pragma unroll
    for (int bt = 0; bt < 4; bt++) {
        int r = wn * 64 + (lane & 15) + bt * 16;
        b_base[bt] = B_OFF + r * 128 + (((sel ^ r) & 7) << 4);
    }

    load_stage(0);
    load_stage(1);

    for (int c = 0; c < NCHUNK_F; c++) {
        if (c + 1 < NCHUNK_F) asm volatile("cp.async.wait_group 1;" ::: "memory");
        else                  asm volatile("cp.async.wait_group 0;" ::: "memory");
        __syncthreads();
        if (c + 2 < NCHUNK_F) load_stage(c + 2);

        const uint32_t sb = sb0 + (c % NSTAGE) * STAGE_BYTES;

#pragma unroll
        for (int ks = 0; ks < 4; ks++) {
            const uint32_t xv = ks << 5;
            uint32_t ah[2][4];
#pragma unroll
            for (int mt = 0; mt < 2; mt++)
                ldsm_x4((sb + a_base[mt]) ^ xv, ah[mt][0], ah[mt][1], ah[mt][2], ah[mt][3]);
            uint32_t bh[8][2];
#pragma unroll
            for (int bt = 0; bt < 4; bt++) {
                uint32_t r0, r1, r2, r3;
                ldsm_x4((sb + b_base[bt]) ^ xv, r0, r1, r2, r3);
                bh[2 * bt][0] = r0; bh[2 * bt][1] = r2;
                bh[2 * bt + 1][0] = r1; bh[2 * bt + 1][1] = r3;
            }
#pragma unroll
            for (int mt = 0; mt < 2; mt++)
#pragma unroll
                for (int nt = 0; nt < 8; nt++)
                    mma16816(acc[mt][nt], ah[mt], bh[nt][0], bh[nt][1]);
        }
    }

    const int ob = (lane & 3) * 2;
#pragma unroll
    for (int mt = 0; mt < 2; mt++) {
#pragma unroll
        for (int half = 0; half < 2; half++) {
            int m = m0 + wm * 32 + mt * 16 + (lane >> 2) + half * 8;
            float* yp = g_Y + (size_t)m * 512 + g * NF + wn * 64;
#pragma unroll
            for (int nt = 0; nt < 8; nt++) {
                float2 v;
                v.x = acc[mt][nt][half * 2 + 0];
                v.y = acc[mt][nt][half * 2 + 1];
                *(float2*)&yp[nt * 8 + ob] = v;
            }
        }
    }
}

// ---------------------------------------------------------------------------
// Combine (unchanged from R7)
// ---------------------------------------------------------------------------
__global__ void combine_kernel(float* __restrict__ out) {
    const int m = blockIdx.x * 8 + (threadIdx.x >> 5);
    if (m >= Mdim) return;
    const int lane = threadIdx.x & 31;

    const float2* y2 = (const float2*)(g_Y + (size_t)m * 512);
    float2 Z0 = y2[lane];
    float2 Z4 = y2[32 + lane];
    float2 R1 = y2[64 + lane];
    float2 I1 = y2[96 + lane];
    float2 R2 = y2[128 + lane];
    float2 I2 = y2[160 + lane];
    float2 R3 = y2[192 + lane];
    float2 I3 = y2[224 + lane];

    const float bx = g_biasK[2 * lane];
    const float by = g_biasK[2 * lane + 1];

    const int b = m / Nn;
    const int n = m - b * Nn;
    float* op = out + (size_t)b * ((size_t)KAa * Nn * Oo) + (size_t)n * Oo + 2 * lane;

    const float C1[8] = {1.f, SQH, 0.f, -SQH, -1.f, -SQH, 0.f, SQH};
    const float S1[8] = {0.f, SQH, 1.f, SQH, 0.f, -SQH, -1.f, -SQH};
    const float C2[8] = {1.f, 0.f, -1.f, 0.f, 1.f, 0.f, -1.f, 0.f};
    const float S2[8] = {0.f, 1.f, 0.f, -1.f, 0.f, 1.f, 0.f, -1.f};
    const float C3[8] = {1.f, -SQH, 0.f, SQH, -1.f, SQH, 0.f, -SQH};
    const float S3[8] = {0.f, SQH, -1.f, SQH, 0.f, -SQH, 1.f, -SQH};

#pragma unroll
    for (int r = 0; r < 8; r++) {
        float sg = (r & 1) ? -1.f : 1.f;
        float2 v;
        v.x = 0.125f * (Z0.x + sg * Z4.x)
            + 0.25f * (C1[r] * R1.x - S1[r] * I1.x
                     + C2[r] * R2.x - S2[r] * I2.x
                     + C3[r] * R3.x - S3[r] * I3.x) + bx;
        v.y = 0.125f * (Z0.y + sg * Z4.y)
            + 0.25f * (C1[r] * R1.y - S1[r] * I1.y
                     + C2[r] * R2.y - S2[r] * I2.y
                     + C3[r] * R3.y - S3[r] * I3.y) + by;
        *(float2*)&op[(size_t)r * (Nn * Oo)] = v;
    }
}

// ---------------------------------------------------------------------------
extern "C" void kernel_launch(void* const* d_in, const int* in_sizes, int n_in,
                              void* d_out, int out_size) {
    const float* signal  = (const float*)d_in[0];
    const float* bary    = (const float*)d_in[1];
    const float* kernels = (const float*)d_in[2];
    const float* bias    = (const float*)d_in[3];
    float* out = (float*)d_out;

    conv_signal_kernel<<<(4 * Nn * Cc / 4 + 255) / 256, 256>>>(signal);
    prep_wb_kernel<<<NBLK * NF, KF>>>(kernels);
    prep_bias_kernel<<<1, Oo>>>(bias);

    gather_fft_kernel<<<Mdim / 32, 256>>>(bary);   // warp = 4 m-rows, 8 warps/CTA

    {
        static int smem_set = 0;
        if (!smem_set) {
            cudaFuncSetAttribute(gemm_mma_kernel,
                                 cudaFuncAttributeMaxDynamicSharedMemorySize, GEMM_SMEM);
            smem_set = 1;
        }
        dim3 grid(NBLK, Mpad / 128);   // (4, 313)
        gemm_mma_kernel<<<grid, 256, GEMM_SMEM>>>();
    }

    combine_kernel<<<Mdim / 8, 256>>>(out);
}